// round 5
// baseline (speedup 1.0000x reference)
#include <cuda_runtime.h>
#include <cuda_bf16.h>

// FocalLossAdaptive: loss = sum_i -(1-pt_i)^gamma_i * logpt_i
//   logpt_i = x[i, t_i] - logsumexp(x[i, :])
//   gamma_i = 5 if pt < 0.2 else 3
// N=4096 rows, C=32000 cols fp32. HBM-bound streaming reduction.
// target is int32 (JAX x64-disabled downcasts the int64 request).

#define C_COLS 32000
#define THREADS 256

__global__ void zero_out_kernel(float* out) {
    if (threadIdx.x == 0) out[0] = 0.0f;
}

__global__ __launch_bounds__(THREADS) void focal_loss_kernel(
    const float* __restrict__ input,
    const int* __restrict__ target,
    float* __restrict__ out)
{
    const int row = blockIdx.x;
    const float4* rowp = reinterpret_cast<const float4*>(input + (size_t)row * C_COLS);
    const int nvec = C_COLS / 4;  // 8000

    // Online logsumexp over this thread's strided slice
    float m = -3.402823466e+38f;
    float s = 0.0f;
    for (int i = threadIdx.x; i < nvec; i += THREADS) {
        float4 v = rowp[i];
        float vm = fmaxf(fmaxf(v.x, v.y), fmaxf(v.z, v.w));
        if (vm > m) {
            s *= __expf(m - vm);
            m = vm;
        }
        s += __expf(v.x - m) + __expf(v.y - m) + __expf(v.z - m) + __expf(v.w - m);
    }

    // Warp combine of (m, s)
    #pragma unroll
    for (int off = 16; off > 0; off >>= 1) {
        float om = __shfl_xor_sync(0xFFFFFFFFu, m, off);
        float os = __shfl_xor_sync(0xFFFFFFFFu, s, off);
        float nm = fmaxf(m, om);
        s = s * __expf(m - nm) + os * __expf(om - nm);
        m = nm;
    }

    // Cross-warp combine via shared memory (8 warps)
    __shared__ float sm_m[THREADS / 32];
    __shared__ float sm_s[THREADS / 32];
    const int wid = threadIdx.x >> 5;
    const int lid = threadIdx.x & 31;
    if (lid == 0) { sm_m[wid] = m; sm_s[wid] = s; }
    __syncthreads();

    if (threadIdx.x == 0) {
        float M = sm_m[0];
        float S = sm_s[0];
        #pragma unroll
        for (int w = 1; w < THREADS / 32; w++) {
            float om = sm_m[w], os = sm_s[w];
            float nm = fmaxf(M, om);
            S = S * __expf(M - nm) + os * __expf(om - nm);
            M = nm;
        }
        const float logZ = M + __logf(S);

        // int32 target; clamp defensively so a bad index shows as rel_err, not IMA
        int t = target[row];
        t = max(0, min(t, C_COLS - 1));
        const float xt = input[(size_t)row * C_COLS + t];
        const float logpt = xt - logZ;
        const float pt = __expf(logpt);
        const float u = 1.0f - pt;
        const float u2 = u * u;
        const float u3 = u2 * u;
        const float u5 = u3 * u2;
        const float w = (pt < 0.2f) ? u5 : u3;  // gamma 5 if pt<0.2, else 3
        const float loss = -w * logpt;
        atomicAdd(out, loss);
    }
}

extern "C" void kernel_launch(void* const* d_in, const int* in_sizes, int n_in,
                              void* d_out, int out_size) {
    const float* input = (const float*)d_in[0];
    const int* target = (const int*)d_in[1];
    float* out = (float*)d_out;

    zero_out_kernel<<<1, 32>>>(out);

    const int n_rows = in_sizes[1];  // 4096 targets
    focal_loss_kernel<<<n_rows, THREADS>>>(input, target, out);
}